// round 9
// baseline (speedup 1.0000x reference)
#include <cuda_runtime.h>
#include <cuda_bf16.h>
#include <cstdint>

#define Bsz 256
#define Ssz 256
#define Esz 256
#define Hsz 1024
#define G4  4096   // 4*H

// ---- step kernel tiling: CTA M64xN64, 4 warps (2x2), warp tile M32xN32 ----
#define BMt 64                  // M tile (batch rows per CTA)
#define HT  16                  // h columns per gate per CTA
#define NT  64                  // N tile = 4 gates * HT
#define KC  64                  // K chunk (bf16 elements = 128 B row)
#define NCHUNK (Hsz / KC)       // 16
#define NSTAGE 3

// ---- smem layout ----
#define A_MAT_BYTES (BMt * KC * 2)                      // 8 KB per matrix
#define B_MAT_BYTES (NT * KC * 2)                       // 8 KB per matrix
#define STAGE_BYTES (2 * A_MAT_BYTES + 2 * B_MAT_BYTES) // 32 KB
#define OFF_AHI 0
#define OFF_ALO (A_MAT_BYTES)
#define OFF_BHI (2 * A_MAT_BYTES)
#define OFF_BLO (2 * A_MAT_BYTES + B_MAT_BYTES)
#define SMEM_TOTAL (NSTAGE * STAGE_BYTES)               // 96 KB -> 2 CTAs/SM
#define DPITCH 68

// ---- device globals (no allocation allowed) ----
__device__ float g_letter_proj[30 * G4];
__device__ float g_state_proj[4 * G4];
__device__ __nv_bfloat16 g_W_hi[(size_t)G4 * Hsz];   // 8 MB
__device__ __nv_bfloat16 g_W_lo[(size_t)G4 * Hsz];   // 8 MB
__device__ __nv_bfloat16 g_h_hi[2][Bsz * Hsz];
__device__ __nv_bfloat16 g_h_lo[2][Bsz * Hsz];
__device__ float g_c[2][Bsz * Hsz];

// ---------------------------------------------------------------------------
// PTX helpers
// ---------------------------------------------------------------------------
__device__ __forceinline__ uint32_t smem_u32(const void* p) {
    uint32_t a;
    asm("{ .reg .u64 t; cvta.to.shared.u64 t, %1; cvt.u32.u64 %0, t; }"
        : "=r"(a) : "l"(p));
    return a;
}
__device__ __forceinline__ void cp16(uint32_t s, const void* g) {
    asm volatile("cp.async.cg.shared.global [%0], [%1], 16;"
                 :: "r"(s), "l"(g) : "memory");
}
#define CP_COMMIT() asm volatile("cp.async.commit_group;" ::: "memory")
#define CP_WAIT1()  asm volatile("cp.async.wait_group 1;" ::: "memory")

__device__ __forceinline__ void ldsm4(uint32_t a, uint32_t* r) {
    asm volatile("ldmatrix.sync.aligned.m8n8.x4.shared.b16 {%0,%1,%2,%3}, [%4];"
                 : "=r"(r[0]), "=r"(r[1]), "=r"(r[2]), "=r"(r[3]) : "r"(a));
}
__device__ __forceinline__ void mma16816(float* c, const uint32_t* a,
                                         const uint32_t* b) {
    asm volatile(
        "mma.sync.aligned.m16n8k16.row.col.f32.bf16.bf16.f32 "
        "{%0,%1,%2,%3}, {%4,%5,%6,%7}, {%8,%9}, {%0,%1,%2,%3};"
        : "+f"(c[0]), "+f"(c[1]), "+f"(c[2]), "+f"(c[3])
        : "r"(a[0]), "r"(a[1]), "r"(a[2]), "r"(a[3]), "r"(b[0]), "r"(b[1]));
}
__device__ __forceinline__ float sigmoidf_(float x) {
    return 1.0f / (1.0f + expf(-x));
}

// ---------------------------------------------------------------------------
// One-time prep: split W_hh into bf16 hi/lo
// ---------------------------------------------------------------------------
__global__ void wsplit_kernel(const float* __restrict__ W) {
    size_t i = ((size_t)blockIdx.x * blockDim.x + threadIdx.x) * 4;
    float4 w = *(const float4*)(W + i);
    float v[4] = {w.x, w.y, w.z, w.w};
    #pragma unroll
    for (int j = 0; j < 4; j++) {
        __nv_bfloat16 hi = __float2bfloat16(v[j]);
        g_W_hi[i + j] = hi;
        g_W_lo[i + j] = __float2bfloat16(v[j] - __bfloat162float(hi));
    }
}

// ---------------------------------------------------------------------------
// One-time prep: x_proj lookup tables (incl. biases), plain [gate*H + h]
// ---------------------------------------------------------------------------
__global__ void proj_kernel(const float* __restrict__ letter_emb,
                            const float* __restrict__ state_emb,
                            const float* __restrict__ W_ih,
                            const float* __restrict__ b_ih,
                            const float* __restrict__ b_hh) {
    int tok  = blockIdx.y;
    int g    = blockIdx.x * 8 + (threadIdx.x >> 5);
    int lane = threadIdx.x & 31;

    const float* emb;
    const float* w;
    if (tok < 30) {
        emb = letter_emb + tok * Esz;
        w   = W_ih + (size_t)g * (2 * Esz);
    } else {
        emb = state_emb + (tok - 30) * Esz;
        w   = W_ih + (size_t)g * (2 * Esz) + Esz;
    }

    float acc = 0.f;
    for (int k = lane; k < Esz; k += 32)
        acc += emb[k] * w[k];
    #pragma unroll
    for (int off = 16; off; off >>= 1)
        acc += __shfl_xor_sync(0xFFFFFFFFu, acc, off);

    if (lane == 0) {
        if (tok < 30)
            g_letter_proj[tok * G4 + g] = acc + b_ih[g] + b_hh[g];
        else
            g_state_proj[(tok - 30) * G4 + g] = acc;
    }
}

// ---------------------------------------------------------------------------
// HMMA LSTM step. grid (64, 4) = 256 CTAs, 128 threads (4 warps, 2x2),
// 2 CTAs/SM: barrier/epilogue phases of the two CTAs overlap, all 148 SMs used.
// D = Ahi*Bhi + Alo*Bhi + Ahi*Blo (fp32 accum). 3-stage cp.async pipeline.
// ---------------------------------------------------------------------------
__global__ void __launch_bounds__(128, 2)
lstm_step_mma(const int* __restrict__ letter_seq,
              const int* __restrict__ state_seq,
              float* __restrict__ out_h,
              float* __restrict__ out_c,
              int s) {
    extern __shared__ char smem[];
    const uint32_t smem_base = smem_u32(smem);

    const int tid = threadIdx.x;
    const int h0  = blockIdx.x * HT;
    const int bm0 = blockIdx.y * BMt;
    const int rbuf = (s & 1) ^ 1;
    const int wbuf = s & 1;

    const int wid = tid >> 5;
    const int l   = tid & 31;
    const int wm  = wid >> 1;         // 0..1 (M)
    const int wn  = wid & 1;          // 0..1 (N)

    float acc[2][4][4];
    #pragma unroll
    for (int i = 0; i < 2; i++)
        #pragma unroll
        for (int j = 0; j < 4; j++)
            #pragma unroll
            for (int k = 0; k < 4; k++)
                acc[i][j][k] = 0.f;

    if (s > 0) {
        // ---- stage-load constants: 128 threads cover 32 KB/stage ----
        // thread t -> row t>>1 (0..63), granules (t&1)*4 .. +3, for A and B
        const int r  = tid >> 1;
        const int gb = (tid & 1) * 4;
        const __nv_bfloat16* hh = g_h_hi[rbuf] + (size_t)(bm0 + r) * Hsz;
        const __nv_bfloat16* hl = g_h_lo[rbuf] + (size_t)(bm0 + r) * Hsz;
        // B row n = r: gate = n>>4, hcol = n&15
        const size_t wrow = (size_t)((r >> 4) * Hsz + h0 + (r & 15)) * Hsz;

        auto load_stage = [&](int ch) {
            const int k0 = ch * KC;
            const uint32_t sb = smem_base
                              + (uint32_t)(ch % NSTAGE) * STAGE_BYTES;
            #pragma unroll
            for (int j = 0; j < 4; j++) {
                const int g = gb + j;
                const uint32_t so = (uint32_t)r * 128
                                  + (uint32_t)(((g ^ (r & 7)) & 7) * 16);
                cp16(sb + OFF_AHI + so, hh + k0 + g * 8);
                cp16(sb + OFF_ALO + so, hl + k0 + g * 8);
                cp16(sb + OFF_BHI + so, g_W_hi + wrow + k0 + g * 8);
                cp16(sb + OFF_BLO + so, g_W_lo + wrow + k0 + g * 8);
            }
        };

        // ---- ldmatrix lane constants ----
        const int a_r0 = wm * 32 + (l & 7) + ((l >> 3) & 1) * 8;  // +16 for mf=1
        const int a_kh = l >> 4;
        const int b_n0 = wn * 32 + (l & 7) + (l >> 4) * 8;        // +16 for x=1
        const int b_kh = (l >> 3) & 1;

        load_stage(0); CP_COMMIT();
        load_stage(1); CP_COMMIT();

        for (int ch = 0; ch < NCHUNK; ch++) {
            CP_WAIT1();
            __syncthreads();
            if (ch + 2 < NCHUNK) load_stage(ch + 2);
            CP_COMMIT();

            const uint32_t sb = smem_base
                              + (uint32_t)(ch % NSTAGE) * STAGE_BYTES;
            #pragma unroll
            for (int ks = 0; ks < 4; ks++) {
                const int agq = ks * 2 + a_kh;
                const int bgq = ks * 2 + b_kh;
                uint32_t ah[2][4], al[2][4], bh[2][4], bl[2][4];
                #pragma unroll
                for (int mf = 0; mf < 2; mf++) {
                    int ar = a_r0 + mf * 16;
                    uint32_t arow = (uint32_t)ar * 128
                                  + (uint32_t)((agq ^ (ar & 7)) * 16);
                    ldsm4(sb + OFF_AHI + arow, ah[mf]);
                    ldsm4(sb + OFF_ALO + arow, al[mf]);
                }
                #pragma unroll
                for (int x = 0; x < 2; x++) {
                    int bn = b_n0 + x * 16;
                    uint32_t brow = (uint32_t)bn * 128
                                  + (uint32_t)((bgq ^ (bn & 7)) * 16);
                    ldsm4(sb + OFF_BHI + brow, bh[x]);
                    ldsm4(sb + OFF_BLO + brow, bl[x]);
                }
                // term-major ordering: reuse distance 4 into each acc quad
                #pragma unroll
                for (int mf = 0; mf < 2; mf++)
                    #pragma unroll
                    for (int x = 0; x < 2; x++) {
                        mma16816(acc[mf][x * 2],     ah[mf], &bh[x][0]);
                        mma16816(acc[mf][x * 2 + 1], ah[mf], &bh[x][2]);
                    }
                #pragma unroll
                for (int mf = 0; mf < 2; mf++)
                    #pragma unroll
                    for (int x = 0; x < 2; x++) {
                        mma16816(acc[mf][x * 2],     al[mf], &bh[x][0]);
                        mma16816(acc[mf][x * 2 + 1], al[mf], &bh[x][2]);
                    }
                #pragma unroll
                for (int mf = 0; mf < 2; mf++)
                    #pragma unroll
                    for (int x = 0; x < 2; x++) {
                        mma16816(acc[mf][x * 2],     ah[mf], &bl[x][0]);
                        mma16816(acc[mf][x * 2 + 1], ah[mf], &bl[x][2]);
                    }
            }
        }

        // ---- dump accums to smem D[64][DPITCH] ----
        __syncthreads();
        float* Dsm = (float*)smem;
        #pragma unroll
        for (int mf = 0; mf < 2; mf++)
            #pragma unroll
            for (int nf = 0; nf < 4; nf++) {
                int m = wm * 32 + mf * 16 + (l >> 2);
                int n = wn * 32 + nf * 8 + (l & 3) * 2;
                *(float2*)&Dsm[m * DPITCH + n] =
                    make_float2(acc[mf][nf][0], acc[mf][nf][1]);
                *(float2*)&Dsm[(m + 8) * DPITCH + n] =
                    make_float2(acc[mf][nf][2], acc[mf][nf][3]);
            }
        __syncthreads();
    }

    // ---- fused LSTM cell epilogue: thread -> (m, 8 h-cols) ----
    {
        const float* Dsm = (const float*)smem;
        const int m    = tid >> 1;         // 0..63
        const int half = tid & 1;          // 8-col half of HT=16
        const int b    = bm0 + m;
        const int lt = letter_seq[b * Ssz + s];
        const int st = state_seq[b * Ssz + s];
        const float* lp = g_letter_proj + (size_t)lt * G4 + h0;
        const float* sp = g_state_proj  + (size_t)st * G4 + h0;
        const size_t base  = (size_t)b * (Ssz * Hsz) + (size_t)s * Hsz + h0;
        const size_t cbase = (size_t)b * Hsz + h0;
        const int hl0 = half * 8;

        float hv[8], cv[8];
        #pragma unroll
        for (int j = 0; j < 8; j++) {
            const int hlc = hl0 + j;
            float pi, pf, pg, po;
            if (s > 0) {
                pi = Dsm[m * DPITCH + 0 * 16 + hlc];
                pf = Dsm[m * DPITCH + 1 * 16 + hlc];
                pg = Dsm[m * DPITCH + 2 * 16 + hlc];
                po = Dsm[m * DPITCH + 3 * 16 + hlc];
            } else {
                pi = pf = pg = po = 0.f;
            }
            pi += lp[hlc]           + sp[hlc];
            pf += lp[Hsz + hlc]     + sp[Hsz + hlc];
            pg += lp[2 * Hsz + hlc] + sp[2 * Hsz + hlc];
            po += lp[3 * Hsz + hlc] + sp[3 * Hsz + hlc];
            float cprev = (s > 0) ? g_c[rbuf][cbase + hlc] : 0.f;
            float c = sigmoidf_(pf) * cprev + sigmoidf_(pi) * tanhf(pg);
            cv[j] = c;
            hv[j] = sigmoidf_(po) * tanhf(c);
        }
        #pragma unroll
        for (int j = 0; j < 2; j++) {
            *(float4*)(out_h + base + hl0 + j * 4) =
                make_float4(hv[j*4], hv[j*4+1], hv[j*4+2], hv[j*4+3]);
            *(float4*)(out_c + base + hl0 + j * 4) =
                make_float4(cv[j*4], cv[j*4+1], cv[j*4+2], cv[j*4+3]);
            *(float4*)(g_c[wbuf] + cbase + hl0 + j * 4) =
                make_float4(cv[j*4], cv[j*4+1], cv[j*4+2], cv[j*4+3]);
        }
        __nv_bfloat162 dh[4], dl[4];
        #pragma unroll
        for (int j = 0; j < 4; j++) {
            float x0 = hv[2*j], x1 = hv[2*j+1];
            __nv_bfloat16 b0 = __float2bfloat16(x0);
            __nv_bfloat16 b1 = __float2bfloat16(x1);
            dh[j] = __nv_bfloat162(b0, b1);
            dl[j] = __nv_bfloat162(__float2bfloat16(x0 - __bfloat162float(b0)),
                                   __float2bfloat16(x1 - __bfloat162float(b1)));
        }
        *(uint4*)(g_h_hi[wbuf] + cbase + hl0) = *(const uint4*)dh;
        *(uint4*)(g_h_lo[wbuf] + cbase + hl0) = *(const uint4*)dl;
    }
}

// ---------------------------------------------------------------------------
extern "C" void kernel_launch(void* const* d_in, const int* in_sizes, int n_in,
                              void* d_out, int out_size) {
    const int*   letter_seq = (const int*)d_in[0];
    const int*   state_seq  = (const int*)d_in[1];
    const float* letter_emb = (const float*)d_in[2];
    const float* state_emb  = (const float*)d_in[3];
    const float* W_ih       = (const float*)d_in[4];
    const float* W_hh       = (const float*)d_in[5];
    const float* b_ih       = (const float*)d_in[6];
    const float* b_hh       = (const float*)d_in[7];

    float* out_h = (float*)d_out;
    float* out_c = out_h + (size_t)Bsz * Ssz * Hsz;

    static int smem_set = 0;
    if (!smem_set) {
        cudaFuncSetAttribute(lstm_step_mma,
                             cudaFuncAttributeMaxDynamicSharedMemorySize,
                             SMEM_TOTAL);
        smem_set = 1;
    }

    wsplit_kernel<<<(G4 * Hsz) / (256 * 4), 256>>>(W_hh);
    proj_kernel<<<dim3(G4 / 8, 34), 256>>>(letter_emb, state_emb, W_ih, b_ih, b_hh);

    for (int s = 0; s < Ssz; s++) {
        lstm_step_mma<<<dim3(Hsz / HT, Bsz / BMt), 128, SMEM_TOTAL>>>(
            letter_seq, state_seq, out_h, out_c, s);
    }
}

// round 10
// speedup vs baseline: 2.8515x; 2.8515x over previous
#include <cuda_runtime.h>
#include <cuda_fp16.h>
#include <cstdint>

#define Bsz 256
#define Ssz 256
#define Esz 256
#define Hsz 1024
#define G4  4096   // 4*H

// ---- step kernel tiling (R4 champion): 8 warps (2x4), warp tile M32xN32 ----
#define BMt 64                  // M tile (batch rows per CTA)
#define HT  32                  // h columns per gate per CTA
#define NT  128                 // N tile = 4 gates * HT
#define KC  64                  // K chunk (fp16 elements = 128 B row)
#define NCHUNK (Hsz / KC)       // 16
#define NSTAGE 3

// ---- smem layout: A single + B hi + B lo ----
#define A_MAT_BYTES (BMt * KC * 2)                      // 8 KB
#define B_MAT_BYTES (NT * KC * 2)                       // 16 KB per matrix
#define STAGE_BYTES (A_MAT_BYTES + 2 * B_MAT_BYTES)     // 40 KB
#define OFF_A   0
#define OFF_BHI (A_MAT_BYTES)
#define OFF_BLO (A_MAT_BYTES + B_MAT_BYTES)
#define SMEM_TOTAL (NSTAGE * STAGE_BYTES)               // 120 KB
#define DPITCH 132
#define LO_SCALE 2048.0f
#define INV_LO_SCALE (1.0f / 2048.0f)

// ---- device globals (no allocation allowed) ----
__device__ float g_letter_proj[30 * G4];
__device__ float g_state_proj[4 * G4];
__device__ __half g_W_hi[(size_t)G4 * Hsz];          // 8 MB
__device__ __half g_W_lo[(size_t)G4 * Hsz];          // 8 MB (scaled by 2^11)
__device__ __half g_h[2][Bsz * Hsz];                 // ping-pong h (fp16)

// ---------------------------------------------------------------------------
// PTX helpers
// ---------------------------------------------------------------------------
__device__ __forceinline__ uint32_t smem_u32(const void* p) {
    uint32_t a;
    asm("{ .reg .u64 t; cvta.to.shared.u64 t, %1; cvt.u32.u64 %0, t; }"
        : "=r"(a) : "l"(p));
    return a;
}
__device__ __forceinline__ void cp16(uint32_t s, const void* g) {
    asm volatile("cp.async.cg.shared.global [%0], [%1], 16;"
                 :: "r"(s), "l"(g) : "memory");
}
#define CP_COMMIT() asm volatile("cp.async.commit_group;" ::: "memory")
#define CP_WAIT1()  asm volatile("cp.async.wait_group 1;" ::: "memory")

__device__ __forceinline__ void ldsm4(uint32_t a, uint32_t* r) {
    asm volatile("ldmatrix.sync.aligned.m8n8.x4.shared.b16 {%0,%1,%2,%3}, [%4];"
                 : "=r"(r[0]), "=r"(r[1]), "=r"(r[2]), "=r"(r[3]) : "r"(a));
}
__device__ __forceinline__ void mma16816(float* c, const uint32_t* a,
                                         const uint32_t* b) {
    asm volatile(
        "mma.sync.aligned.m16n8k16.row.col.f32.f16.f16.f32 "
        "{%0,%1,%2,%3}, {%4,%5,%6,%7}, {%8,%9}, {%0,%1,%2,%3};"
        : "+f"(c[0]), "+f"(c[1]), "+f"(c[2]), "+f"(c[3])
        : "r"(a[0]), "r"(a[1]), "r"(a[2]), "r"(a[3]), "r"(b[0]), "r"(b[1]));
}
__device__ __forceinline__ float sigmoidf_(float x) {
    return 1.0f / (1.0f + expf(-x));
}

// ---------------------------------------------------------------------------
// One-time prep: split W_hh into fp16 hi + fp16 lo*2^11 (avoids subnormals)
// ---------------------------------------------------------------------------
__global__ void wsplit_kernel(const float* __restrict__ W) {
    size_t i = ((size_t)blockIdx.x * blockDim.x + threadIdx.x) * 4;
    float4 w = *(const float4*)(W + i);
    float v[4] = {w.x, w.y, w.z, w.w};
    #pragma unroll
    for (int j = 0; j < 4; j++) {
        __half hi = __float2half(v[j]);
        g_W_hi[i + j] = hi;
        g_W_lo[i + j] = __float2half((v[j] - __half2float(hi)) * LO_SCALE);
    }
}

// ---------------------------------------------------------------------------
// One-time prep: x_proj lookup tables (incl. biases), plain [gate*H + h]
// ---------------------------------------------------------------------------
__global__ void proj_kernel(const float* __restrict__ letter_emb,
                            const float* __restrict__ state_emb,
                            const float* __restrict__ W_ih,
                            const float* __restrict__ b_ih,
                            const float* __restrict__ b_hh) {
    int tok  = blockIdx.y;
    int g    = blockIdx.x * 8 + (threadIdx.x >> 5);
    int lane = threadIdx.x & 31;

    const float* emb;
    const float* w;
    if (tok < 30) {
        emb = letter_emb + tok * Esz;
        w   = W_ih + (size_t)g * (2 * Esz);
    } else {
        emb = state_emb + (tok - 30) * Esz;
        w   = W_ih + (size_t)g * (2 * Esz) + Esz;
    }

    float acc = 0.f;
    for (int k = lane; k < Esz; k += 32)
        acc += emb[k] * w[k];
    #pragma unroll
    for (int off = 16; off; off >>= 1)
        acc += __shfl_xor_sync(0xFFFFFFFFu, acc, off);

    if (lane == 0) {
        if (tok < 30)
            g_letter_proj[tok * G4 + g] = acc + b_ih[g] + b_hh[g];
        else
            g_state_proj[(tok - 30) * G4 + g] = acc;
    }
}

// ---------------------------------------------------------------------------
// HMMA LSTM step. grid (32, 4) = 128 CTAs, 256 threads (8 warps, 2x4).
// D = A*Bhi + (A*Blo_scaled)*2^-11, fp16 operands, fp32 accum.
// 3-stage cp.async pipeline, one __syncthreads per chunk (R4 structure).
// ---------------------------------------------------------------------------
__global__ void __launch_bounds__(256, 1)
lstm_step_mma(const int* __restrict__ letter_seq,
              const int* __restrict__ state_seq,
              float* __restrict__ out_h,
              float* __restrict__ out_c,
              int s) {
    extern __shared__ char smem[];
    const uint32_t smem_base = smem_u32(smem);

    const int tid = threadIdx.x;
    const int h0  = blockIdx.x * HT;
    const int bm0 = blockIdx.y * BMt;
    const int rbuf = (s & 1) ^ 1;
    const int wbuf = s & 1;

    const int wid = tid >> 5;
    const int l   = tid & 31;
    const int wm  = wid >> 2;         // 0..1
    const int wn  = wid & 3;          // 0..3

    float acc[2][4][4];               // hi term
    float acc2[2][4][4];              // lo term (scaled by 2^11)
    #pragma unroll
    for (int i = 0; i < 2; i++)
        #pragma unroll
        for (int j = 0; j < 4; j++)
            #pragma unroll
            for (int k = 0; k < 4; k++) {
                acc[i][j][k] = 0.f;
                acc2[i][j][k] = 0.f;
            }

    if (s > 0) {
        // ---- stage-load constants ----
        const int r  = tid >> 3;                 // 0..31
        const int gq = tid & 7;                  // 16B granule in 128B row
        const uint32_t sw = (uint32_t)((gq ^ (r & 7)) * 16);
        const __half* hsrc = g_h[rbuf] + (size_t)(bm0 + r) * Hsz + gq * 8;
        const size_t wrow = (size_t)(h0 + r) * Hsz + gq * 8;

        auto load_stage = [&](int ch) {
            const int k0 = ch * KC;
            const uint32_t sb = smem_base + (uint32_t)(ch % NSTAGE) * STAGE_BYTES;
            cp16(sb + OFF_A + r * 128 + sw,        hsrc + k0);
            cp16(sb + OFF_A + (r + 32) * 128 + sw, hsrc + k0 + 32 * Hsz);
            #pragma unroll
            for (int gate = 0; gate < 4; gate++) {
                const size_t off = wrow + (size_t)gate * Hsz * Hsz + k0;
                const uint32_t sn = (uint32_t)(gate * 32 + r) * 128 + sw;
                cp16(sb + OFF_BHI + sn, g_W_hi + off);
                cp16(sb + OFF_BLO + sn, g_W_lo + off);
            }
        };

        // ---- ldmatrix lane constants ----
        const int a_r0 = wm * 32 + (l & 7) + ((l >> 3) & 1) * 8;  // +16 for mf=1
        const int a_kh = l >> 4;
        const int b_n0 = wn * 32 + (l & 7) + (l >> 4) * 8;        // +16 for x=1
        const int b_kh = (l >> 3) & 1;

        load_stage(0); CP_COMMIT();
        load_stage(1); CP_COMMIT();

        for (int ch = 0; ch < NCHUNK; ch++) {
            CP_WAIT1();
            __syncthreads();
            if (ch + 2 < NCHUNK) load_stage(ch + 2);
            CP_COMMIT();

            const uint32_t sb = smem_base + (uint32_t)(ch % NSTAGE) * STAGE_BYTES;
            #pragma unroll
            for (int ks = 0; ks < 4; ks++) {
                const int agq = ks * 2 + a_kh;
                const int bgq = ks * 2 + b_kh;
                uint32_t a[2][4], bh[2][4], bl[2][4];
                #pragma unroll
                for (int mf = 0; mf < 2; mf++) {
                    int ar = a_r0 + mf * 16;
                    uint32_t arow = (uint32_t)ar * 128
                                  + (uint32_t)((agq ^ (ar & 7)) * 16);
                    ldsm4(sb + OFF_A + arow, a[mf]);
                }
                #pragma unroll
                for (int x = 0; x < 2; x++) {
                    int bn = b_n0 + x * 16;
                    uint32_t brow = (uint32_t)bn * 128
                                  + (uint32_t)((bgq ^ (bn & 7)) * 16);
                    ldsm4(sb + OFF_BHI + brow, bh[x]);
                    ldsm4(sb + OFF_BLO + brow, bl[x]);
                }
                // term-major: hi term then lo term (separate accumulators)
                #pragma unroll
                for (int mf = 0; mf < 2; mf++)
                    #pragma unroll
                    for (int x = 0; x < 2; x++) {
                        mma16816(acc[mf][x * 2],     a[mf], &bh[x][0]);
                        mma16816(acc[mf][x * 2 + 1], a[mf], &bh[x][2]);
                    }
                #pragma unroll
                for (int mf = 0; mf < 2; mf++)
                    #pragma unroll
                    for (int x = 0; x < 2; x++) {
                        mma16816(acc2[mf][x * 2],     a[mf], &bl[x][0]);
                        mma16816(acc2[mf][x * 2 + 1], a[mf], &bl[x][2]);
                    }
            }
        }

        // ---- combine terms, dump to smem D[64][DPITCH] ----
        __syncthreads();
        float* Dsm = (float*)smem;
        #pragma unroll
        for (int mf = 0; mf < 2; mf++)
            #pragma unroll
            for (int nf = 0; nf < 4; nf++) {
                int m = wm * 32 + mf * 16 + (l >> 2);
                int n = wn * 32 + nf * 8 + (l & 3) * 2;
                float d0 = acc[mf][nf][0] + acc2[mf][nf][0] * INV_LO_SCALE;
                float d1 = acc[mf][nf][1] + acc2[mf][nf][1] * INV_LO_SCALE;
                float d2 = acc[mf][nf][2] + acc2[mf][nf][2] * INV_LO_SCALE;
                float d3 = acc[mf][nf][3] + acc2[mf][nf][3] * INV_LO_SCALE;
                *(float2*)&Dsm[m * DPITCH + n] = make_float2(d0, d1);
                *(float2*)&Dsm[(m + 8) * DPITCH + n] = make_float2(d2, d3);
            }
        __syncthreads();
    }

    // ---- fused LSTM cell epilogue ----
    {
        const float* Dsm = (const float*)smem;
        const int m  = tid >> 2;          // 0..63
        const int hq = tid & 3;           // 8-col group
        const int b  = bm0 + m;
        const int lt = letter_seq[b * Ssz + s];
        const int st = state_seq[b * Ssz + s];
        const float* lp = g_letter_proj + (size_t)lt * G4 + h0;
        const float* sp = g_state_proj  + (size_t)st * G4 + h0;
        const size_t base = (size_t)b * (Ssz * Hsz) + (size_t)s * Hsz + h0;
        const int hl0 = hq * 8;

        float hv[8], cv[8];
        #pragma unroll
        for (int j = 0; j < 8; j++) {
            const int hlc = hl0 + j;
            float pi, pf, pg, po;
            if (s > 0) {
                pi = Dsm[m * DPITCH + 0 * 32 + hlc];
                pf = Dsm[m * DPITCH + 1 * 32 + hlc];
                pg = Dsm[m * DPITCH + 2 * 32 + hlc];
                po = Dsm[m * DPITCH + 3 * 32 + hlc];
            } else {
                pi = pf = pg = po = 0.f;
            }
            pi += lp[hlc]           + sp[hlc];
            pf += lp[Hsz + hlc]     + sp[Hsz + hlc];
            pg += lp[2 * Hsz + hlc] + sp[2 * Hsz + hlc];
            po += lp[3 * Hsz + hlc] + sp[3 * Hsz + hlc];
            float cprev = (s > 0) ? out_c[base - Hsz + hlc] : 0.f;
            float c = sigmoidf_(pf) * cprev + sigmoidf_(pi) * tanhf(pg);
            cv[j] = c;
            hv[j] = sigmoidf_(po) * tanhf(c);
        }
        #pragma unroll
        for (int j = 0; j < 2; j++) {
            *(float4*)(out_h + base + hl0 + j * 4) =
                make_float4(hv[j*4], hv[j*4+1], hv[j*4+2], hv[j*4+3]);
            *(float4*)(out_c + base + hl0 + j * 4) =
                make_float4(cv[j*4], cv[j*4+1], cv[j*4+2], cv[j*4+3]);
        }
        // fp16 h for next step's A
        __half2 dh[4];
        #pragma unroll
        for (int j = 0; j < 4; j++)
            dh[j] = __floats2half2_rn(hv[2 * j], hv[2 * j + 1]);
        *(uint4*)(g_h[wbuf] + (size_t)b * Hsz + h0 + hl0) = *(const uint4*)dh;
    }
}

// ---------------------------------------------------------------------------
extern "C" void kernel_launch(void* const* d_in, const int* in_sizes, int n_in,
                              void* d_out, int out_size) {
    const int*   letter_seq = (const int*)d_in[0];
    const int*   state_seq  = (const int*)d_in[1];
    const float* letter_emb = (const float*)d_in[2];
    const float* state_emb  = (const float*)d_in[3];
    const float* W_ih       = (const float*)d_in[4];
    const float* W_hh       = (const float*)d_in[5];
    const float* b_ih       = (const float*)d_in[6];
    const float* b_hh       = (const float*)d_in[7];

    float* out_h = (float*)d_out;
    float* out_c = out_h + (size_t)Bsz * Ssz * Hsz;

    static int smem_set = 0;
    if (!smem_set) {
        cudaFuncSetAttribute(lstm_step_mma,
                             cudaFuncAttributeMaxDynamicSharedMemorySize,
                             SMEM_TOTAL);
        smem_set = 1;
    }

    wsplit_kernel<<<(G4 * Hsz) / (256 * 4), 256>>>(W_hh);
    proj_kernel<<<dim3(G4 / 8, 34), 256>>>(letter_emb, state_emb, W_ih, b_ih, b_hh);

    for (int s = 0; s < Ssz; s++) {
        lstm_step_mma<<<dim3(Hsz / HT, Bsz / BMt), 256, SMEM_TOTAL>>>(
            letter_seq, state_seq, out_h, out_c, s);
    }
}

// round 12
// speedup vs baseline: 4.0972x; 1.4368x over previous
#include <cuda_runtime.h>
#include <cuda_fp16.h>
#include <cstdint>

#define Bsz 256
#define Ssz 256
#define Esz 256
#define Hsz 1024
#define G4  4096   // 4*H

// ---- step kernel tiling (R4 champion): 8 warps (2x4), warp tile M32xN32 ----
#define BMt 64                  // M tile (batch rows per CTA)
#define HT  32                  // h columns per gate per CTA
#define NT  128                 // N tile = 4 gates * HT
#define KC  64                  // K chunk (fp16 elements = 128 B row)
#define NCHUNK (Hsz / KC)       // 16
#define NSTAGE 3

// ---- smem layout: A + B (single fp16 term) ----
#define A_MAT_BYTES (BMt * KC * 2)                      // 8 KB
#define B_MAT_BYTES (NT * KC * 2)                       // 16 KB
#define STAGE_BYTES (A_MAT_BYTES + B_MAT_BYTES)         // 24 KB
#define OFF_A   0
#define OFF_B   (A_MAT_BYTES)
#define SMEM_TOTAL (NSTAGE * STAGE_BYTES)               // 72 KB
#define DPITCH 132

// ---- device globals (no allocation allowed) ----
__device__ float g_letter_proj[30 * G4];
__device__ float g_state_proj[4 * G4];
__device__ __half g_W[(size_t)G4 * Hsz];             // 8 MB fp16 W_hh
__device__ __half g_h[2][Bsz * Hsz];                 // ping-pong h (fp16)

// ---------------------------------------------------------------------------
// PTX helpers
// ---------------------------------------------------------------------------
__device__ __forceinline__ uint32_t smem_u32(const void* p) {
    uint32_t a;
    asm("{ .reg .u64 t; cvta.to.shared.u64 t, %1; cvt.u32.u64 %0, t; }"
        : "=r"(a) : "l"(p));
    return a;
}
__device__ __forceinline__ void cp16(uint32_t s, const void* g) {
    asm volatile("cp.async.cg.shared.global [%0], [%1], 16;"
                 :: "r"(s), "l"(g) : "memory");
}
#define CP_COMMIT() asm volatile("cp.async.commit_group;" ::: "memory")
#define CP_WAIT1()  asm volatile("cp.async.wait_group 1;" ::: "memory")

__device__ __forceinline__ void ldsm4(uint32_t a, uint32_t* r) {
    asm volatile("ldmatrix.sync.aligned.m8n8.x4.shared.b16 {%0,%1,%2,%3}, [%4];"
                 : "=r"(r[0]), "=r"(r[1]), "=r"(r[2]), "=r"(r[3]) : "r"(a));
}
__device__ __forceinline__ void mma16816(float* c, const uint32_t* a,
                                         const uint32_t* b) {
    asm volatile(
        "mma.sync.aligned.m16n8k16.row.col.f32.f16.f16.f32 "
        "{%0,%1,%2,%3}, {%4,%5,%6,%7}, {%8,%9}, {%0,%1,%2,%3};"
        : "+f"(c[0]), "+f"(c[1]), "+f"(c[2]), "+f"(c[3])
        : "r"(a[0]), "r"(a[1]), "r"(a[2]), "r"(a[3]), "r"(b[0]), "r"(b[1]));
}
__device__ __forceinline__ float sigmoidf_(float x) {
    return 1.0f / (1.0f + expf(-x));
}

// ---------------------------------------------------------------------------
// One-time prep: convert W_hh to fp16
// ---------------------------------------------------------------------------
__global__ void wconv_kernel(const float* __restrict__ W) {
    size_t i = ((size_t)blockIdx.x * blockDim.x + threadIdx.x) * 4;
    float4 w = *(const float4*)(W + i);
    __half2 h0 = __floats2half2_rn(w.x, w.y);
    __half2 h1 = __floats2half2_rn(w.z, w.w);
    *(uint2*)(g_W + i) = make_uint2(*(uint32_t*)&h0, *(uint32_t*)&h1);
}

// ---------------------------------------------------------------------------
// One-time prep: x_proj lookup tables (incl. biases), plain [gate*H + h]
// ---------------------------------------------------------------------------
__global__ void proj_kernel(const float* __restrict__ letter_emb,
                            const float* __restrict__ state_emb,
                            const float* __restrict__ W_ih,
                            const float* __restrict__ b_ih,
                            const float* __restrict__ b_hh) {
    int tok  = blockIdx.y;
    int g    = blockIdx.x * 8 + (threadIdx.x >> 5);
    int lane = threadIdx.x & 31;

    const float* emb;
    const float* w;
    if (tok < 30) {
        emb = letter_emb + tok * Esz;
        w   = W_ih + (size_t)g * (2 * Esz);
    } else {
        emb = state_emb + (tok - 30) * Esz;
        w   = W_ih + (size_t)g * (2 * Esz) + Esz;
    }

    float acc = 0.f;
    for (int k = lane; k < Esz; k += 32)
        acc += emb[k] * w[k];
    #pragma unroll
    for (int off = 16; off; off >>= 1)
        acc += __shfl_xor_sync(0xFFFFFFFFu, acc, off);

    if (lane == 0) {
        if (tok < 30)
            g_letter_proj[tok * G4 + g] = acc + b_ih[g] + b_hh[g];
        else
            g_state_proj[(tok - 30) * G4 + g] = acc;
    }
}

// ---------------------------------------------------------------------------
// HMMA LSTM step. grid (32, 4) = 128 CTAs, 256 threads (8 warps, 2x4).
// D = A * B, fp16 operands, fp32 accum (single term).
// 3-stage cp.async pipeline, one __syncthreads per chunk.
// ---------------------------------------------------------------------------
__global__ void __launch_bounds__(256, 1)
lstm_step_mma(const int* __restrict__ letter_seq,
              const int* __restrict__ state_seq,
              float* __restrict__ out_h,
              float* __restrict__ out_c,
              int s) {
    extern __shared__ char smem[];
    const uint32_t smem_base = smem_u32(smem);

    const int tid = threadIdx.x;
    const int h0  = blockIdx.x * HT;
    const int bm0 = blockIdx.y * BMt;
    const int rbuf = (s & 1) ^ 1;
    const int wbuf = s & 1;

    const int wid = tid >> 5;
    const int l   = tid & 31;
    const int wm  = wid >> 2;         // 0..1
    const int wn  = wid & 3;          // 0..3

    float acc[2][4][4];
    #pragma unroll
    for (int i = 0; i < 2; i++)
        #pragma unroll
        for (int j = 0; j < 4; j++)
            #pragma unroll
            for (int k = 0; k < 4; k++)
                acc[i][j][k] = 0.f;

    if (s > 0) {
        // ---- stage-load constants ----
        const int r  = tid >> 3;                 // 0..31
        const int gq = tid & 7;                  // 16B granule in 128B row
        const uint32_t sw = (uint32_t)((gq ^ (r & 7)) * 16);
        const __half* hsrc = g_h[rbuf] + (size_t)(bm0 + r) * Hsz + gq * 8;
        const size_t wrow = (size_t)(h0 + r) * Hsz + gq * 8;

        auto load_stage = [&](int ch) {
            const int k0 = ch * KC;
            const uint32_t sb = smem_base + (uint32_t)(ch % NSTAGE) * STAGE_BYTES;
            cp16(sb + OFF_A + r * 128 + sw,        hsrc + k0);
            cp16(sb + OFF_A + (r + 32) * 128 + sw, hsrc + k0 + 32 * Hsz);
            #pragma unroll
            for (int gate = 0; gate < 4; gate++) {
                const size_t off = wrow + (size_t)gate * Hsz * Hsz + k0;
                const uint32_t sn = (uint32_t)(gate * 32 + r) * 128 + sw;
                cp16(sb + OFF_B + sn, g_W + off);
            }
        };

        // ---- ldmatrix lane constants ----
        const int a_r0 = wm * 32 + (l & 7) + ((l >> 3) & 1) * 8;  // +16 for mf=1
        const int a_kh = l >> 4;
        const int b_n0 = wn * 32 + (l & 7) + (l >> 4) * 8;        // +16 for x=1
        const int b_kh = (l >> 3) & 1;

        load_stage(0); CP_COMMIT();
        load_stage(1); CP_COMMIT();

        for (int ch = 0; ch < NCHUNK; ch++) {
            CP_WAIT1();
            __syncthreads();
            if (ch + 2 < NCHUNK) load_stage(ch + 2);
            CP_COMMIT();

            const uint32_t sb = smem_base + (uint32_t)(ch % NSTAGE) * STAGE_BYTES;
            #pragma unroll
            for (int ks = 0; ks < 4; ks++) {
                const int agq = ks * 2 + a_kh;
                const int bgq = ks * 2 + b_kh;
                uint32_t a[2][4], b[2][4];
                #pragma unroll
                for (int mf = 0; mf < 2; mf++) {
                    int ar = a_r0 + mf * 16;
                    uint32_t arow = (uint32_t)ar * 128
                                  + (uint32_t)((agq ^ (ar & 7)) * 16);
                    ldsm4(sb + OFF_A + arow, a[mf]);
                }
                #pragma unroll
                for (int x = 0; x < 2; x++) {
                    int bn = b_n0 + x * 16;
                    uint32_t brow = (uint32_t)bn * 128
                                  + (uint32_t)((bgq ^ (bn & 7)) * 16);
                    ldsm4(sb + OFF_B + brow, b[x]);
                }
                // 8 MMAs per ks, each acc quad touched once (reuse distance 8)
                #pragma unroll
                for (int mf = 0; mf < 2; mf++)
                    #pragma unroll
                    for (int x = 0; x < 2; x++) {
                        mma16816(acc[mf][x * 2],     a[mf], &b[x][0]);
                        mma16816(acc[mf][x * 2 + 1], a[mf], &b[x][2]);
                    }
            }
        }

        // ---- dump accums to smem D[64][DPITCH] ----
        __syncthreads();
        float* Dsm = (float*)smem;
        #pragma unroll
        for (int mf = 0; mf < 2; mf++)
            #pragma unroll
            for (int nf = 0; nf < 4; nf++) {
                int m = wm * 32 + mf * 16 + (l >> 2);
                int n = wn * 32 + nf * 8 + (l & 3) * 2;
                *(float2*)&Dsm[m * DPITCH + n] =
                    make_float2(acc[mf][nf][0], acc[mf][nf][1]);
                *(float2*)&Dsm[(m + 8) * DPITCH + n] =
                    make_float2(acc[mf][nf][2], acc[mf][nf][3]);
            }
        __syncthreads();
    }

    // ---- fused LSTM cell epilogue ----
    {
        const float* Dsm = (const float*)smem;
        const int m  = tid >> 2;          // 0..63
        const int hq = tid & 3;           // 8-col group
        const int b  = bm0 + m;
        const int lt = letter_seq[b * Ssz + s];
        const int st = state_seq[b * Ssz + s];
        const float* lp = g_letter_proj + (size_t)lt * G4 + h0;
        const float* sp = g_state_proj  + (size_t)st * G4 + h0;
        const size_t base = (size_t)b * (Ssz * Hsz) + (size_t)s * Hsz + h0;
        const int hl0 = hq * 8;

        float hv[8], cv[8];
        #pragma unroll
        for (int j = 0; j < 8; j++) {
            const int hlc = hl0 + j;
            float pi, pf, pg, po;
            if (s > 0) {
                pi = Dsm[m * DPITCH + 0 * 32 + hlc];
                pf = Dsm[m * DPITCH + 1 * 32 + hlc];
                pg = Dsm[m * DPITCH + 2 * 32 + hlc];
                po = Dsm[m * DPITCH + 3 * 32 + hlc];
            } else {
                pi = pf = pg = po = 0.f;
            }
            pi += lp[hlc]           + sp[hlc];
            pf += lp[Hsz + hlc]     + sp[Hsz + hlc];
            pg += lp[2 * Hsz + hlc] + sp[2 * Hsz + hlc];
            po += lp[3 * Hsz + hlc] + sp[3 * Hsz + hlc];
            float cprev = (s > 0) ? out_c[base - Hsz + hlc] : 0.f;
            float c = sigmoidf_(pf) * cprev + sigmoidf_(pi) * tanhf(pg);
            cv[j] = c;
            hv[j] = sigmoidf_(po) * tanhf(c);
        }
        #pragma unroll
        for (int j = 0; j < 2; j++) {
            *(float4*)(out_h + base + hl0 + j * 4) =
                make_float4(hv[j*4], hv[j*4+1], hv[j*4+2], hv[j*4+3]);
            *(float4*)(out_c + base + hl0 + j * 4) =
                make_float4(cv[j*4], cv[j*4+1], cv[j*4+2], cv[j*4+3]);
        }
        // fp16 h for next step's A
        __half2 dh[4];
        #pragma unroll
        for (int j = 0; j < 4; j++)
            dh[j] = __floats2half2_rn(hv[2 * j], hv[2 * j + 1]);
        *(uint4*)(g_h[wbuf] + (size_t)b * Hsz + h0 + hl0) = *(const uint4*)dh;
    }
}

// ---------------------------------------------------------------------------
extern "C" void kernel_launch(void* const* d_in, const int* in_sizes, int n_in,
                              void* d_out, int out_size) {
    const int*   letter_seq = (const int*)d_in[0];
    const int*   state_seq  = (const int*)d_in[1];
    const float* letter_emb = (const float*)d_in[2];
    const float* state_emb  = (const float*)d_in[3];
    const float* W_ih       = (const float*)d_in[4];
    const float* W_hh       = (const float*)d_in[5];
    const float* b_ih       = (const float*)d_in[6];
    const float* b_hh       = (const float*)d_in[7];

    float* out_h = (float*)d_out;
    float* out_c = out_h + (size_t)Bsz * Ssz * Hsz;

    static int smem_set = 0;
    if (!smem_set) {
        cudaFuncSetAttribute(lstm_step_mma,
                             cudaFuncAttributeMaxDynamicSharedMemorySize,
                             SMEM_TOTAL);
        smem_set = 1;
    }

    wconv_kernel<<<(G4 * Hsz) / (256 * 4), 256>>>(W_hh);
    proj_kernel<<<dim3(G4 / 8, 34), 256>>>(letter_emb, state_emb, W_ih, b_ih, b_hh);

    for (int s = 0; s < Ssz; s++) {
        lstm_step_mma<<<dim3(Hsz / HT, Bsz / BMt), 256, SMEM_TOTAL>>>(
            letter_seq, state_seq, out_h, out_c, s);
    }
}

// round 13
// speedup vs baseline: 4.1393x; 1.0103x over previous
#include <cuda_runtime.h>
#include <cuda_fp16.h>
#include <cstdint>

#define Bsz 256
#define Ssz 256
#define Esz 256
#define Hsz 1024
#define G4  4096   // 4*H
#define NCTA 128

// ---- tiling (R12 champion): 8 warps (2x4), warp tile M32xN32 ----
#define BMt 64
#define HT  32
#define NT  128
#define KC  64
#define NCHUNK (Hsz / KC)       // 16
#define NSTAGE 3

// ---- smem layout ----
#define A_MAT_BYTES (BMt * KC * 2)                  // 8 KB
#define B_MAT_BYTES (NT * KC * 2)                   // 16 KB
#define STAGE_BYTES (A_MAT_BYTES + B_MAT_BYTES)     // 24 KB
#define OFF_A   0
#define OFF_B   (A_MAT_BYTES)
#define SMEM_TOTAL (NSTAGE * STAGE_BYTES)           // 72 KB
#define DPITCH 132

// ---- device globals ----
__device__ float g_letter_proj[30 * G4];
__device__ float g_state_proj[4 * G4];
__device__ __half g_W[(size_t)G4 * Hsz];
__device__ __half g_h[2][Bsz * Hsz];
__device__ unsigned g_bar;

// ---------------------------------------------------------------------------
__device__ __forceinline__ uint32_t smem_u32(const void* p) {
    uint32_t a;
    asm("{ .reg .u64 t; cvta.to.shared.u64 t, %1; cvt.u32.u64 %0, t; }"
        : "=r"(a) : "l"(p));
    return a;
}
__device__ __forceinline__ void cp16(uint32_t s, const void* g) {
    asm volatile("cp.async.cg.shared.global [%0], [%1], 16;"
                 :: "r"(s), "l"(g) : "memory");
}
#define CP_COMMIT() asm volatile("cp.async.commit_group;" ::: "memory")
#define CP_WAIT0()  asm volatile("cp.async.wait_group 0;" ::: "memory")
#define CP_WAIT1()  asm volatile("cp.async.wait_group 1;" ::: "memory")

__device__ __forceinline__ void ldsm4(uint32_t a, uint32_t* r) {
    asm volatile("ldmatrix.sync.aligned.m8n8.x4.shared.b16 {%0,%1,%2,%3}, [%4];"
                 : "=r"(r[0]), "=r"(r[1]), "=r"(r[2]), "=r"(r[3]) : "r"(a));
}
__device__ __forceinline__ void mma16816(float* c, const uint32_t* a,
                                         const uint32_t* b) {
    asm volatile(
        "mma.sync.aligned.m16n8k16.row.col.f32.f16.f16.f32 "
        "{%0,%1,%2,%3}, {%4,%5,%6,%7}, {%8,%9}, {%0,%1,%2,%3};"
        : "+f"(c[0]), "+f"(c[1]), "+f"(c[2]), "+f"(c[3])
        : "r"(a[0]), "r"(a[1]), "r"(a[2]), "r"(a[3]), "r"(b[0]), "r"(b[1]));
}
__device__ __forceinline__ float sigmoidf_(float x) {
    return 1.0f / (1.0f + expf(-x));
}

// ---------------------------------------------------------------------------
__global__ void reset_kernel() { g_bar = 0; }

__global__ void wconv_kernel(const float* __restrict__ W) {
    size_t i = ((size_t)blockIdx.x * blockDim.x + threadIdx.x) * 4;
    float4 w = *(const float4*)(W + i);
    __half2 h0 = __floats2half2_rn(w.x, w.y);
    __half2 h1 = __floats2half2_rn(w.z, w.w);
    *(uint2*)(g_W + i) = make_uint2(*(uint32_t*)&h0, *(uint32_t*)&h1);
}

__global__ void proj_kernel(const float* __restrict__ letter_emb,
                            const float* __restrict__ state_emb,
                            const float* __restrict__ W_ih,
                            const float* __restrict__ b_ih,
                            const float* __restrict__ b_hh) {
    int tok  = blockIdx.y;
    int g    = blockIdx.x * 8 + (threadIdx.x >> 5);
    int lane = threadIdx.x & 31;

    const float* emb;
    const float* w;
    if (tok < 30) {
        emb = letter_emb + tok * Esz;
        w   = W_ih + (size_t)g * (2 * Esz);
    } else {
        emb = state_emb + (tok - 30) * Esz;
        w   = W_ih + (size_t)g * (2 * Esz) + Esz;
    }

    float acc = 0.f;
    for (int k = lane; k < Esz; k += 32)
        acc += emb[k] * w[k];
    #pragma unroll
    for (int off = 16; off; off >>= 1)
        acc += __shfl_xor_sync(0xFFFFFFFFu, acc, off);

    if (lane == 0) {
        if (tok < 30)
            g_letter_proj[tok * G4 + g] = acc + b_ih[g] + b_hh[g];
        else
            g_state_proj[(tok - 30) * G4 + g] = acc;
    }
}

// ---------------------------------------------------------------------------
// Persistent LSTM: all 256 steps in one kernel. grid (32,4)=128 CTAs (1/SM,
// guaranteed co-resident), 256 threads. Inter-step sync: atomic global
// barrier; W(B) chunks for the next step are prefetched during the spin
// (they don't depend on h). c-state carried in registers.
// ---------------------------------------------------------------------------
__global__ void __launch_bounds__(256, 1)
lstm_persist(const int* __restrict__ letter_seq,
             const int* __restrict__ state_seq,
             float* __restrict__ out_h,
             float* __restrict__ out_c) {
    extern __shared__ char smem[];
    const uint32_t smem_base = smem_u32(smem);

    const int tid = threadIdx.x;
    const int h0  = blockIdx.x * HT;
    const int bm0 = blockIdx.y * BMt;

    const int wid = tid >> 5;
    const int l   = tid & 31;
    const int wm  = wid >> 2;
    const int wn  = wid & 3;

    // ---- stage-load constants ----
    const int r  = tid >> 3;
    const int gq = tid & 7;
    const uint32_t sw = (uint32_t)((gq ^ (r & 7)) * 16);
    const __half* hbuf[2] = {
        g_h[0] + (size_t)(bm0 + r) * Hsz + gq * 8,
        g_h[1] + (size_t)(bm0 + r) * Hsz + gq * 8
    };
    const size_t wrow = (size_t)(h0 + r) * Hsz + gq * 8;

    auto loadA = [&](int ch, const __half* hsrc) {
        const int k0 = ch * KC;
        const uint32_t sb = smem_base + (uint32_t)(ch % NSTAGE) * STAGE_BYTES;
        cp16(sb + OFF_A + r * 128 + sw,        hsrc + k0);
        cp16(sb + OFF_A + (r + 32) * 128 + sw, hsrc + k0 + 32 * Hsz);
    };
    auto loadB = [&](int ch) {
        const int k0 = ch * KC;
        const uint32_t sb = smem_base + (uint32_t)(ch % NSTAGE) * STAGE_BYTES;
        #pragma unroll
        for (int gate = 0; gate < 4; gate++) {
            const size_t off = wrow + (size_t)gate * Hsz * Hsz + k0;
            const uint32_t sn = (uint32_t)(gate * 32 + r) * 128 + sw;
            cp16(sb + OFF_B + sn, g_W + off);
        }
    };

    // ---- ldmatrix lane constants ----
    const int a_r0 = wm * 32 + (l & 7) + ((l >> 3) & 1) * 8;
    const int a_kh = l >> 4;
    const int b_n0 = wn * 32 + (l & 7) + (l >> 4) * 8;
    const int b_kh = (l >> 3) & 1;

    // ---- epilogue constants ----
    const int m  = tid >> 2;
    const int hq = tid & 3;
    const int eb = bm0 + m;
    const int hl0 = hq * 8;
    const int seqbase = eb * Ssz;
    size_t obase = (size_t)eb * (Ssz * Hsz) + h0;   // + s*Hsz per step
    __half* hst[2] = { g_h[0] + (size_t)eb * Hsz + h0 + hl0,
                       g_h[1] + (size_t)eb * Hsz + h0 + hl0 };

    float creg[8];
    #pragma unroll
    for (int j = 0; j < 8; j++) creg[j] = 0.f;

    unsigned target = NCTA;

    for (int s = 0; s < Ssz; s++) {
        float acc[2][4][4];
        #pragma unroll
        for (int i = 0; i < 2; i++)
            #pragma unroll
            for (int j = 0; j < 4; j++)
                #pragma unroll
                for (int k = 0; k < 4; k++)
                    acc[i][j][k] = 0.f;

        if (s > 0) {
            const __half* hcur = hbuf[(s - 1) & 1];
            // stages 0,1 already in flight (B group pre-barrier, A group post)
            auto compute = [&](int ch) {
                const uint32_t sb = smem_base
                                  + (uint32_t)(ch % NSTAGE) * STAGE_BYTES;
                #pragma unroll
                for (int ks = 0; ks < 4; ks++) {
                    const int agq = ks * 2 + a_kh;
                    const int bgq = ks * 2 + b_kh;
                    uint32_t a[2][4], b[2][4];
                    #pragma unroll
                    for (int mf = 0; mf < 2; mf++) {
                        int ar = a_r0 + mf * 16;
                        uint32_t arow = (uint32_t)ar * 128
                                      + (uint32_t)((agq ^ (ar & 7)) * 16);
                        ldsm4(sb + OFF_A + arow, a[mf]);
                    }
                    #pragma unroll
                    for (int x = 0; x < 2; x++) {
                        int bn = b_n0 + x * 16;
                        uint32_t brow = (uint32_t)bn * 128
                                      + (uint32_t)((bgq ^ (bn & 7)) * 16);
                        ldsm4(sb + OFF_B + brow, b[x]);
                    }
                    #pragma unroll
                    for (int mf = 0; mf < 2; mf++)
                        #pragma unroll
                        for (int x = 0; x < 2; x++) {
                            mma16816(acc[mf][x * 2],     a[mf], &b[x][0]);
                            mma16816(acc[mf][x * 2 + 1], a[mf], &b[x][2]);
                        }
                }
            };

            // peeled chunk 0: wait for prefetch groups (B01, A01)
            CP_WAIT0();
            __syncthreads();
            loadA(2, hcur); loadB(2); CP_COMMIT();
            compute(0);
            for (int ch = 1; ch < NCHUNK; ch++) {
                CP_WAIT1();
                __syncthreads();
                if (ch + 2 < NCHUNK) { loadA(ch + 2, hcur); loadB(ch + 2); }
                CP_COMMIT();
                compute(ch);
            }

            // ---- dump accums to smem D ----
            __syncthreads();
            float* Dsm = (float*)smem;
            #pragma unroll
            for (int mf = 0; mf < 2; mf++)
                #pragma unroll
                for (int nf = 0; nf < 4; nf++) {
                    int mm = wm * 32 + mf * 16 + (l >> 2);
                    int nn = wn * 32 + nf * 8 + (l & 3) * 2;
                    *(float2*)&Dsm[mm * DPITCH + nn] =
                        make_float2(acc[mf][nf][0], acc[mf][nf][1]);
                    *(float2*)&Dsm[(mm + 8) * DPITCH + nn] =
                        make_float2(acc[mf][nf][2], acc[mf][nf][3]);
                }
            __syncthreads();
        }

        // ---- fused LSTM cell epilogue (c carried in registers) ----
        {
            const float* Dsm = (const float*)smem;
            const int lt = letter_seq[seqbase + s];
            const int st = state_seq[seqbase + s];
            const float* lp = g_letter_proj + (size_t)lt * G4 + h0;
            const float* sp = g_state_proj  + (size_t)st * G4 + h0;

            float hv[8];
            #pragma unroll
            for (int j = 0; j < 8; j++) {
                const int hlc = hl0 + j;
                float pi, pf, pg, po;
                if (s > 0) {
                    pi = Dsm[m * DPITCH + 0 * 32 + hlc];
                    pf = Dsm[m * DPITCH + 1 * 32 + hlc];
                    pg = Dsm[m * DPITCH + 2 * 32 + hlc];
                    po = Dsm[m * DPITCH + 3 * 32 + hlc];
                } else {
                    pi = pf = pg = po = 0.f;
                }
                pi += lp[hlc]           + sp[hlc];
                pf += lp[Hsz + hlc]     + sp[Hsz + hlc];
                pg += lp[2 * Hsz + hlc] + sp[2 * Hsz + hlc];
                po += lp[3 * Hsz + hlc] + sp[3 * Hsz + hlc];
                float c = sigmoidf_(pf) * creg[j] + sigmoidf_(pi) * tanhf(pg);
                creg[j] = c;
                hv[j] = sigmoidf_(po) * tanhf(c);
            }
            #pragma unroll
            for (int j = 0; j < 2; j++) {
                *(float4*)(out_h + obase + hl0 + j * 4) =
                    make_float4(hv[j*4], hv[j*4+1], hv[j*4+2], hv[j*4+3]);
                *(float4*)(out_c + obase + hl0 + j * 4) =
                    make_float4(creg[j*4], creg[j*4+1], creg[j*4+2], creg[j*4+3]);
            }
            __half2 dh[4];
            #pragma unroll
            for (int j = 0; j < 4; j++)
                dh[j] = __floats2half2_rn(hv[2 * j], hv[2 * j + 1]);
            *(uint4*)hst[s & 1] = *(const uint4*)dh;
        }
        obase += Hsz;

        // ---- inter-step global barrier + prefetch overlap ----
        if (s < Ssz - 1) {
            __threadfence();                 // release h stores
            __syncthreads();                 // CTA done (incl. Dsm reads)
            if (tid == 0) atomicAdd(&g_bar, 1u);
            // prefetch next step's W tiles during the barrier (h-independent)
            loadB(0); loadB(1); CP_COMMIT();
            if (tid == 0) {
                while (*(volatile unsigned*)&g_bar < target) { }
            }
            target += NCTA;
            __syncthreads();
            __threadfence();                 // acquire peers' h
            const __half* hnext = hbuf[s & 1];
            loadA(0, hnext); loadA(1, hnext); CP_COMMIT();
        }
    }
}

// ---------------------------------------------------------------------------
extern "C" void kernel_launch(void* const* d_in, const int* in_sizes, int n_in,
                              void* d_out, int out_size) {
    const int*   letter_seq = (const int*)d_in[0];
    const int*   state_seq  = (const int*)d_in[1];
    const float* letter_emb = (const float*)d_in[2];
    const float* state_emb  = (const float*)d_in[3];
    const float* W_ih       = (const float*)d_in[4];
    const float* W_hh       = (const float*)d_in[5];
    const float* b_ih       = (const float*)d_in[6];
    const float* b_hh       = (const float*)d_in[7];

    float* out_h = (float*)d_out;
    float* out_c = out_h + (size_t)Bsz * Ssz * Hsz;

    static int smem_set = 0;
    if (!smem_set) {
        cudaFuncSetAttribute(lstm_persist,
                             cudaFuncAttributeMaxDynamicSharedMemorySize,
                             SMEM_TOTAL);
        smem_set = 1;
    }

    reset_kernel<<<1, 1>>>();
    wconv_kernel<<<(G4 * Hsz) / (256 * 4), 256>>>(W_hh);
    proj_kernel<<<dim3(G4 / 8, 34), 256>>>(letter_emb, state_emb,
                                           W_ih, b_ih, b_hh);
    lstm_persist<<<dim3(Hsz / HT, Bsz / BMt), 256, SMEM_TOTAL>>>(
        letter_seq, state_seq, out_h, out_c);
}

// round 16
// speedup vs baseline: 4.7694x; 1.1522x over previous
#include <cuda_runtime.h>
#include <cuda_fp16.h>
#include <cstdint>

#define Bsz 256
#define Ssz 256
#define Esz 256
#define Hsz 1024
#define G4  4096   // 4*H
#define NCTA 128

// ---- tiling: 8 warps (2x4), warp tile M32xN32, CTA M64xN128 ----
#define BMt 64
#define HT  32
#define NT  128
#define KC  64
#define NCHUNK (Hsz / KC)       // 16
#define NSTAGE 7
#define DEPTH  6                // prefetch depth (chunks ahead)

// ---- smem layout ----
#define A_MAT_BYTES (BMt * KC * 2)                  // 8 KB
#define B_MAT_BYTES (NT * KC * 2)                   // 16 KB
#define STAGE_BYTES (A_MAT_BYTES + B_MAT_BYTES)     // 24 KB
#define OFF_A   0
#define OFF_B   (A_MAT_BYTES)
#define SMEM_TOTAL (NSTAGE * STAGE_BYTES)           // 168 KB
#define DPITCH 132

// ---- device globals ----
__device__ float g_letter_proj[30 * G4];
__device__ float g_state_proj[4 * G4];
__device__ __half g_W[(size_t)G4 * Hsz];
__device__ __half g_h[2][Bsz * Hsz];
__device__ unsigned g_bar;

// ---------------------------------------------------------------------------
__device__ __forceinline__ uint32_t smem_u32(const void* p) {
    uint32_t a;
    asm("{ .reg .u64 t; cvta.to.shared.u64 t, %1; cvt.u32.u64 %0, t; }"
        : "=r"(a) : "l"(p));
    return a;
}
__device__ __forceinline__ void cp16(uint32_t s, const void* g) {
    asm volatile("cp.async.cg.shared.global [%0], [%1], 16;"
                 :: "r"(s), "l"(g) : "memory");
}
#define CP_COMMIT() asm volatile("cp.async.commit_group;" ::: "memory")
#define CP_WAIT(n)  asm volatile("cp.async.wait_group " #n ";" ::: "memory")

__device__ __forceinline__ void ldsm4(uint32_t a, uint32_t* r) {
    asm volatile("ldmatrix.sync.aligned.m8n8.x4.shared.b16 {%0,%1,%2,%3}, [%4];"
                 : "=r"(r[0]), "=r"(r[1]), "=r"(r[2]), "=r"(r[3]) : "r"(a));
}
__device__ __forceinline__ void mma16816(float* c, const uint32_t* a,
                                         const uint32_t* b) {
    asm volatile(
        "mma.sync.aligned.m16n8k16.row.col.f32.f16.f16.f32 "
        "{%0,%1,%2,%3}, {%4,%5,%6,%7}, {%8,%9}, {%0,%1,%2,%3};"
        : "+f"(c[0]), "+f"(c[1]), "+f"(c[2]), "+f"(c[3])
        : "r"(a[0]), "r"(a[1]), "r"(a[2]), "r"(a[3]), "r"(b[0]), "r"(b[1]));
}
__device__ __forceinline__ float sigmoidf_(float x) {
    return 1.0f / (1.0f + expf(-x));
}

// ---------------------------------------------------------------------------
__global__ void reset_kernel() { g_bar = 0; }

__global__ void wconv_kernel(const float* __restrict__ W) {
    size_t i = ((size_t)blockIdx.x * blockDim.x + threadIdx.x) * 4;
    float4 w = *(const float4*)(W + i);
    __half2 h0 = __floats2half2_rn(w.x, w.y);
    __half2 h1 = __floats2half2_rn(w.z, w.w);
    *(uint2*)(g_W + i) = make_uint2(*(uint32_t*)&h0, *(uint32_t*)&h1);
}

__global__ void proj_kernel(const float* __restrict__ letter_emb,
                            const float* __restrict__ state_emb,
                            const float* __restrict__ W_ih,
                            const float* __restrict__ b_ih,
                            const float* __restrict__ b_hh) {
    int tok  = blockIdx.y;
    int g    = blockIdx.x * 8 + (threadIdx.x >> 5);
    int lane = threadIdx.x & 31;

    const float* emb;
    const float* w;
    if (tok < 30) {
        emb = letter_emb + tok * Esz;
        w   = W_ih + (size_t)g * (2 * Esz);
    } else {
        emb = state_emb + (tok - 30) * Esz;
        w   = W_ih + (size_t)g * (2 * Esz) + Esz;
    }

    float acc = 0.f;
    for (int k = lane; k < Esz; k += 32)
        acc += emb[k] * w[k];
    #pragma unroll
    for (int off = 16; off; off >>= 1)
        acc += __shfl_xor_sync(0xFFFFFFFFu, acc, off);

    if (lane == 0) {
        if (tok < 30)
            g_letter_proj[tok * G4 + g] = acc + b_ih[g] + b_hh[g];
        else
            g_state_proj[(tok - 30) * G4 + g] = acc;
    }
}

// ---------------------------------------------------------------------------
// Persistent LSTM, deep pipeline. 128 CTAs (1/SM), 256 threads.
// Per step (s>0) group ledger:
//   pre-spin:  B0..B5  (6 groups, W only — h-independent)
//   post-spin: A0..A5  (6 groups)
//   loop ch=0..9: combined G(ch+6) (10 groups)
//   wait_group 5 for ch=0..9 retires exactly the group(s) chunk ch needs;
//   tail ch=10..15: descending waits 5..0, no loads.
// ---------------------------------------------------------------------------
__global__ void __launch_bounds__(256, 1)
lstm_persist(const int* __restrict__ letter_seq,
             const int* __restrict__ state_seq,
             float* __restrict__ out_h,
             float* __restrict__ out_c) {
    extern __shared__ char smem[];
    const uint32_t smem_base = smem_u32(smem);

    const int tid = threadIdx.x;
    const int h0  = blockIdx.x * HT;
    const int bm0 = blockIdx.y * BMt;

    const int wid = tid >> 5;
    const int l   = tid & 31;
    const int wm  = wid >> 2;
    const int wn  = wid & 3;

    // ---- stage-load constants ----
    const int r  = tid >> 3;
    const int gq = tid & 7;
    const uint32_t sw = (uint32_t)((gq ^ (r & 7)) * 16);
    const __half* hbuf[2] = {
        g_h[0] + (size_t)(bm0 + r) * Hsz + gq * 8,
        g_h[1] + (size_t)(bm0 + r) * Hsz + gq * 8
    };
    const size_t wrow = (size_t)(h0 + r) * Hsz + gq * 8;

    auto loadA = [&](int ch, const __half* hsrc) {
        const int k0 = ch * KC;
        const uint32_t sb = smem_base + (uint32_t)(ch % NSTAGE) * STAGE_BYTES;
        cp16(sb + OFF_A + r * 128 + sw,        hsrc + k0);
        cp16(sb + OFF_A + (r + 32) * 128 + sw, hsrc + k0 + 32 * Hsz);
    };
    auto loadB = [&](int ch) {
        const int k0 = ch * KC;
        const uint32_t sb = smem_base + (uint32_t)(ch % NSTAGE) * STAGE_BYTES;
        #pragma unroll
        for (int gate = 0; gate < 4; gate++) {
            const size_t off = wrow + (size_t)gate * Hsz * Hsz + k0;
            const uint32_t sn = (uint32_t)(gate * 32 + r) * 128 + sw;
            cp16(sb + OFF_B + sn, g_W + off);
        }
    };

    // ---- ldmatrix lane constants ----
    const int a_r0 = wm * 32 + (l & 7) + ((l >> 3) & 1) * 8;
    const int a_kh = l >> 4;
    const int b_n0 = wn * 32 + (l & 7) + (l >> 4) * 8;
    const int b_kh = (l >> 3) & 1;

    // ---- epilogue constants ----
    const int m  = tid >> 2;
    const int hq = tid & 3;
    const int eb = bm0 + m;
    const int hl0 = hq * 8;
    const int seqbase = eb * Ssz;
    size_t obase = (size_t)eb * (Ssz * Hsz) + h0;
    __half* hst[2] = { g_h[0] + (size_t)eb * Hsz + h0 + hl0,
                       g_h[1] + (size_t)eb * Hsz + h0 + hl0 };

    float creg[8];
    #pragma unroll
    for (int j = 0; j < 8; j++) creg[j] = 0.f;

    unsigned target = NCTA;

    for (int s = 0; s < Ssz; s++) {
        float acc[2][4][4];
        #pragma unroll
        for (int i = 0; i < 2; i++)
            #pragma unroll
            for (int j = 0; j < 4; j++)
                #pragma unroll
                for (int k = 0; k < 4; k++)
                    acc[i][j][k] = 0.f;

        if (s > 0) {
            const __half* hcur = hbuf[(s - 1) & 1];
            auto compute = [&](int ch) {
                const uint32_t sb = smem_base
                                  + (uint32_t)(ch % NSTAGE) * STAGE_BYTES;
                #pragma unroll
                for (int ks = 0; ks < 4; ks++) {
                    const int agq = ks * 2 + a_kh;
                    const int bgq = ks * 2 + b_kh;
                    uint32_t a[2][4], b[2][4];
                    #pragma unroll
                    for (int mf = 0; mf < 2; mf++) {
                        int ar = a_r0 + mf * 16;
                        uint32_t arow = (uint32_t)ar * 128
                                      + (uint32_t)((agq ^ (ar & 7)) * 16);
                        ldsm4(sb + OFF_A + arow, a[mf]);
                    }
                    #pragma unroll
                    for (int x = 0; x < 2; x++) {
                        int bn = b_n0 + x * 16;
                        uint32_t brow = (uint32_t)bn * 128
                                      + (uint32_t)((bgq ^ (bn & 7)) * 16);
                        ldsm4(sb + OFF_B + brow, b[x]);
                    }
                    #pragma unroll
                    for (int mf = 0; mf < 2; mf++)
                        #pragma unroll
                        for (int x = 0; x < 2; x++) {
                            mma16816(acc[mf][x * 2],     a[mf], &b[x][0]);
                            mma16816(acc[mf][x * 2 + 1], a[mf], &b[x][2]);
                        }
                }
            };

            // main loop: 10 iterations with prefetch, uniform wait_group 5
            for (int ch = 0; ch < NCHUNK - DEPTH; ch++) {
                CP_WAIT(5);
                __syncthreads();
                loadA(ch + DEPTH, hcur); loadB(ch + DEPTH);
                CP_COMMIT();
                compute(ch);
            }
            // tail: descending waits, no loads (no stage-reuse hazard)
            CP_WAIT(5); __syncthreads(); compute(10);
            CP_WAIT(4); __syncthreads(); compute(11);
            CP_WAIT(3); __syncthreads(); compute(12);
            CP_WAIT(2); __syncthreads(); compute(13);
            CP_WAIT(1); __syncthreads(); compute(14);
            CP_WAIT(0); __syncthreads(); compute(15);

            // ---- dump accums to smem D ----
            __syncthreads();
            float* Dsm = (float*)smem;
            #pragma unroll
            for (int mf = 0; mf < 2; mf++)
                #pragma unroll
                for (int nf = 0; nf < 4; nf++) {
                    int mm = wm * 32 + mf * 16 + (l >> 2);
                    int nn = wn * 32 + nf * 8 + (l & 3) * 2;
                    *(float2*)&Dsm[mm * DPITCH + nn] =
                        make_float2(acc[mf][nf][0], acc[mf][nf][1]);
                    *(float2*)&Dsm[(mm + 8) * DPITCH + nn] =
                        make_float2(acc[mf][nf][2], acc[mf][nf][3]);
                }
            __syncthreads();
        }

        // ---- fused LSTM cell epilogue (c carried in registers) ----
        {
            const float* Dsm = (const float*)smem;
            const int lt = letter_seq[seqbase + s];
            const int st = state_seq[seqbase + s];
            const float* lp = g_letter_proj + (size_t)lt * G4 + h0;
            const float* sp = g_state_proj  + (size_t)st * G4 + h0;

            float hv[8];
            #pragma unroll
            for (int j = 0; j < 8; j++) {
                const int hlc = hl0 + j;
                float pi, pf, pg, po;
                if (s > 0) {
                    pi = Dsm[m * DPITCH + 0 * 32 + hlc];
                    pf = Dsm[m * DPITCH + 1 * 32 + hlc];
                    pg = Dsm[m * DPITCH + 2 * 32 + hlc];
                    po = Dsm[m * DPITCH + 3 * 32 + hlc];
                } else {
                    pi = pf = pg = po = 0.f;
                }
                pi += lp[hlc]           + sp[hlc];
                pf += lp[Hsz + hlc]     + sp[Hsz + hlc];
                pg += lp[2 * Hsz + hlc] + sp[2 * Hsz + hlc];
                po += lp[3 * Hsz + hlc] + sp[3 * Hsz + hlc];
                float c = sigmoidf_(pf) * creg[j] + sigmoidf_(pi) * tanhf(pg);
                creg[j] = c;
                hv[j] = sigmoidf_(po) * tanhf(c);
            }
            #pragma unroll
            for (int j = 0; j < 2; j++) {
                *(float4*)(out_h + obase + hl0 + j * 4) =
                    make_float4(hv[j*4], hv[j*4+1], hv[j*4+2], hv[j*4+3]);
                *(float4*)(out_c + obase + hl0 + j * 4) =
                    make_float4(creg[j*4], creg[j*4+1], creg[j*4+2], creg[j*4+3]);
            }
            __half2 dh[4];
            #pragma unroll
            for (int j = 0; j < 4; j++)
                dh[j] = __floats2half2_rn(hv[2 * j], hv[2 * j + 1]);
            *(uint4*)hst[s & 1] = *(const uint4*)dh;
        }
        obase += Hsz;

        // ---- inter-step global barrier + deep prefetch overlap ----
        if (s < Ssz - 1) {
            __threadfence();                 // release h stores
            __syncthreads();                 // all warps done with Dsm
            if (tid == 0) atomicAdd(&g_bar, 1u);
            // W tiles for next step's first DEPTH chunks (h-independent)
            #pragma unroll
            for (int ch = 0; ch < DEPTH; ch++) { loadB(ch); CP_COMMIT(); }
            if (tid == 0) {
                while (*(volatile unsigned*)&g_bar < target) { }
            }
            target += NCTA;
            __syncthreads();
            __threadfence();                 // acquire peers' h
            const __half* hnext = hbuf[s & 1];
            #pragma unroll
            for (int ch = 0; ch < DEPTH; ch++) { loadA(ch, hnext); CP_COMMIT(); }
        }
    }
}

// ---------------------------------------------------------------------------
extern "C" void kernel_launch(void* const* d_in, const int* in_sizes, int n_in,
                              void* d_out, int out_size) {
    const int*   letter_seq = (const int*)d_in[0];
    const int*   state_seq  = (const int*)d_in[1];
    const float* letter_emb = (const float*)d_in[2];
    const float* state_emb  = (const float*)d_in[3];
    const float* W_ih       = (const float*)d_in[4];
    const float* W_hh       = (const float*)d_in[5];
    const float* b_ih       = (const float*)d_in[6];
    const float* b_hh       = (const float*)d_in[7];

    float* out_h = (float*)d_out;
    float* out_c = out_h + (size_t)Bsz * Ssz * Hsz;

    static int smem_set = 0;
    if (!smem_set) {
        cudaFuncSetAttribute(lstm_persist,
                             cudaFuncAttributeMaxDynamicSharedMemorySize,
                             SMEM_TOTAL);
        smem_set = 1;
    }

    reset_kernel<<<1, 1>>>();
    wconv_kernel<<<(G4 * Hsz) / (256 * 4), 256>>>(W_hh);
    proj_kernel<<<dim3(G4 / 8, 34), 256>>>(letter_emb, state_emb,
                                           W_ih, b_ih, b_hh);
    lstm_persist<<<dim3(Hsz / HT, Bsz / BMt), 256, SMEM_TOTAL>>>(
        letter_seq, state_seq, out_h, out_c);
}